// round 1
// baseline (speedup 1.0000x reference)
#include <cuda_runtime.h>
#include <cuda_bf16.h>
#include <math.h>

// Problem constants
#define LSEQ 48
#define BATCH 8192
#define EDIM 50
#define HDIM 512
#define VDIM 128
#define KA   (HDIM + EDIM)   // 562 real K
#define KP   576             // padded K (multiple of 16)
#define NG   (4 * HDIM)      // 2048 packed gate columns

// ---------------- scratch (static __device__ arrays; no allocation) ----------
__device__ float g_Wp[(size_t)NG * KP];          // packed weights [n=h*4+g][KP], zero padded
__device__ float g_bsum[NG];                     // b_ih + b_hh in packed order
__device__ float g_Hall[(size_t)LSEQ * BATCH * HDIM];  // h_t for every step (805 MB)
__device__ float g_C[(size_t)BATCH * HDIM];      // running cell state

// ---------------- helpers ----------------------------------------------------
__device__ __forceinline__ unsigned long long pk2(float lo, float hi) {
    unsigned long long r;
    asm("mov.b64 %0, {%1, %2};" : "=l"(r) : "f"(lo), "f"(hi));
    return r;
}
__device__ __forceinline__ void upk2(unsigned long long v, float &lo, float &hi) {
    asm("mov.b64 {%0, %1}, %2;" : "=f"(lo), "=f"(hi) : "l"(v));
}
__device__ __forceinline__ void fma2(unsigned long long &d, unsigned long long a, unsigned long long b) {
    asm("fma.rn.f32x2 %0, %1, %2, %0;" : "+l"(d) : "l"(a), "l"(b));
}
__device__ __forceinline__ float sigm(float x) { return 1.0f / (1.0f + expf(-x)); }

// ---------------- weight repack ----------------------------------------------
// Wp[n][k]: n = h*4 + g  (g in PyTorch order i,f,g,o); k<512 -> W_hh[g*H+h][k];
// 512<=k<562 -> W_ih[g*H+h][k-512]; else 0.  bsum[n] = b_ih+b_hh.
__global__ void repack_kernel(const float* __restrict__ W_ih,
                              const float* __restrict__ W_hh,
                              const float* __restrict__ b_ih,
                              const float* __restrict__ b_hh) {
    const size_t total = (size_t)NG * KP;
    for (size_t i = (size_t)blockIdx.x * blockDim.x + threadIdx.x; i < total;
         i += (size_t)gridDim.x * blockDim.x) {
        int n = (int)(i / KP), k = (int)(i % KP);
        int h = n >> 2, g = n & 3;
        int row = g * HDIM + h;
        float v = 0.0f;
        if (k < HDIM)            v = W_hh[(size_t)row * HDIM + k];
        else if (k < HDIM + EDIM) v = W_ih[(size_t)row * EDIM + (k - HDIM)];
        g_Wp[i] = v;
    }
    int j = blockIdx.x * blockDim.x + threadIdx.x;
    if (j < NG) {
        int h = j >> 2, g = j & 3;
        int row = g * HDIM + h;
        g_bsum[j] = b_ih[row] + b_hh[row];
    }
}

// ---------------- fused gate GEMM + LSTM cell (one time step) -----------------
// C[b][n] = sum_k A[b][k] * Wp[n][k],  A = [h_prev | emb[idx_t[b]]]
// Tile: BM=64, BN=64 (=16 h * 4 gates), BK=16, 128 threads, per-thread 8x4.
__global__ __launch_bounds__(128)
void lstm_step_kernel(int t,
                      const float* __restrict__ h0,
                      const float* __restrict__ c0,
                      const int* __restrict__ input,
                      const float* __restrict__ emb) {
    __shared__ float sA[16][64];
    __shared__ float sB[16][64];
    __shared__ int   sIdx[64];

    const int tid = threadIdx.x;
    const int bm0 = blockIdx.x * 64;   // batch tile base
    const int n0  = blockIdx.y * 64;   // packed-gate column base

    const float* hprev = (t == 0) ? h0 : (g_Hall + (size_t)(t - 1) * BATCH * HDIM);
    const float* csrc  = (t == 0) ? c0 : g_C;
    float* hout = g_Hall + (size_t)t * BATCH * HDIM;
    const int* idx_t = input + (size_t)t * BATCH;

    if (tid < 64) sIdx[tid] = idx_t[bm0 + tid];

    const int lm = tid & 63;          // loader row (A: batch; B: n)
    const int lk = (tid >> 6) * 8;    // loader k offset within tile (0 or 8)

    const int m0 = (tid >> 4) * 8;    // micro-tile row base
    const int cg = tid & 15;          // column group = local h index
    const int nc = cg * 4;            // local n base (4 gates)

    unsigned long long acc[4][4];
    #pragma unroll
    for (int i = 0; i < 4; ++i)
        #pragma unroll
        for (int j = 0; j < 4; ++j) acc[i][j] = 0ULL;

    const int KT = KP / 16;  // 36
    for (int kt = 0; kt < KT; ++kt) {
        const int k0 = kt * 16;
        __syncthreads();
        // ---- load A tile (transposed into sA[k][m]) ----
        if (k0 < HDIM) {
            const float4* src = reinterpret_cast<const float4*>(
                hprev + (size_t)(bm0 + lm) * HDIM + k0 + lk);
            float4 v0 = src[0], v1 = src[1];
            sA[lk + 0][lm] = v0.x; sA[lk + 1][lm] = v0.y;
            sA[lk + 2][lm] = v0.z; sA[lk + 3][lm] = v0.w;
            sA[lk + 4][lm] = v1.x; sA[lk + 5][lm] = v1.y;
            sA[lk + 6][lm] = v1.z; sA[lk + 7][lm] = v1.w;
        } else {
            const float* er = emb + (size_t)sIdx[lm] * EDIM;
            const int e0 = k0 - HDIM + lk;
            #pragma unroll
            for (int j = 0; j < 8; ++j) {
                int e = e0 + j;
                sA[lk + j][lm] = (e < EDIM) ? er[e] : 0.0f;
            }
        }
        // ---- load B tile ----
        {
            const float4* src = reinterpret_cast<const float4*>(
                g_Wp + (size_t)(n0 + lm) * KP + k0 + lk);
            float4 v0 = src[0], v1 = src[1];
            sB[lk + 0][lm] = v0.x; sB[lk + 1][lm] = v0.y;
            sB[lk + 2][lm] = v0.z; sB[lk + 3][lm] = v0.w;
            sB[lk + 4][lm] = v1.x; sB[lk + 5][lm] = v1.y;
            sB[lk + 6][lm] = v1.z; sB[lk + 7][lm] = v1.w;
        }
        __syncthreads();
        // ---- compute ----
        #pragma unroll
        for (int kk = 0; kk < 16; ++kk) {
            float4 a0 = *reinterpret_cast<const float4*>(&sA[kk][m0]);
            float4 a1 = *reinterpret_cast<const float4*>(&sA[kk][m0 + 4]);
            float4 bv = *reinterpret_cast<const float4*>(&sB[kk][nc]);
            unsigned long long ap[4] = { pk2(a0.x, a0.y), pk2(a0.z, a0.w),
                                         pk2(a1.x, a1.y), pk2(a1.z, a1.w) };
            unsigned long long bp[4] = { pk2(bv.x, bv.x), pk2(bv.y, bv.y),
                                         pk2(bv.z, bv.z), pk2(bv.w, bv.w) };
            #pragma unroll
            for (int i = 0; i < 4; ++i)
                #pragma unroll
                for (int j = 0; j < 4; ++j)
                    fma2(acc[i][j], ap[i], bp[j]);
        }
    }

    // ---- epilogue: bias + LSTM cell, write c and h ----
    const float4 bb = *reinterpret_cast<const float4*>(&g_bsum[n0 + nc]);
    const int hglob = (n0 + nc) >> 2;   // global hidden index
    #pragma unroll
    for (int i2 = 0; i2 < 4; ++i2) {
        float lo[4], hi[4];
        #pragma unroll
        for (int j = 0; j < 4; ++j) upk2(acc[i2][j], lo[j], hi[j]);
        const int r0 = bm0 + m0 + 2 * i2;
        // row r0 (lo), row r0+1 (hi)
        #pragma unroll
        for (int p = 0; p < 2; ++p) {
            const int r = r0 + p;
            const float* gv = p ? hi : lo;
            float gi = gv[0] + bb.x;
            float gf = gv[1] + bb.y;
            float gg = gv[2] + bb.z;
            float go = gv[3] + bb.w;
            const size_t off = (size_t)r * HDIM + hglob;
            float co = csrc[off];
            float cn = sigm(gf) * co + sigm(gi) * tanhf(gg);
            float hn = sigm(go) * tanhf(cn);
            g_C[off] = cn;
            hout[off] = hn;
        }
    }
}

// ---------------- batched output projection -----------------------------------
// scores[m][v] = sum_k Hall[m][k] * W_out[v][k] + b_out[v],  m = t*B+b
__global__ __launch_bounds__(128)
void out_gemm_kernel(const float* __restrict__ Wout,
                     const float* __restrict__ bout,
                     float* __restrict__ out) {
    __shared__ float sA[16][64];
    __shared__ float sB[16][64];

    const int tid = threadIdx.x;
    const int bm0 = blockIdx.x * 64;   // row tile over L*B
    const int n0  = blockIdx.y * 64;   // v tile (0 or 64)

    const int lm = tid & 63;
    const int lk = (tid >> 6) * 8;
    const int m0 = (tid >> 4) * 8;
    const int nc = (tid & 15) * 4;

    unsigned long long acc[4][4];
    #pragma unroll
    for (int i = 0; i < 4; ++i)
        #pragma unroll
        for (int j = 0; j < 4; ++j) acc[i][j] = 0ULL;

    for (int kt = 0; kt < HDIM / 16; ++kt) {
        const int k0 = kt * 16;
        __syncthreads();
        {
            const float4* src = reinterpret_cast<const float4*>(
                g_Hall + (size_t)(bm0 + lm) * HDIM + k0 + lk);
            float4 v0 = src[0], v1 = src[1];
            sA[lk + 0][lm] = v0.x; sA[lk + 1][lm] = v0.y;
            sA[lk + 2][lm] = v0.z; sA[lk + 3][lm] = v0.w;
            sA[lk + 4][lm] = v1.x; sA[lk + 5][lm] = v1.y;
            sA[lk + 6][lm] = v1.z; sA[lk + 7][lm] = v1.w;
        }
        {
            const float4* src = reinterpret_cast<const float4*>(
                Wout + (size_t)(n0 + lm) * HDIM + k0 + lk);
            float4 v0 = src[0], v1 = src[1];
            sB[lk + 0][lm] = v0.x; sB[lk + 1][lm] = v0.y;
            sB[lk + 2][lm] = v0.z; sB[lk + 3][lm] = v0.w;
            sB[lk + 4][lm] = v1.x; sB[lk + 5][lm] = v1.y;
            sB[lk + 6][lm] = v1.z; sB[lk + 7][lm] = v1.w;
        }
        __syncthreads();
        #pragma unroll
        for (int kk = 0; kk < 16; ++kk) {
            float4 a0 = *reinterpret_cast<const float4*>(&sA[kk][m0]);
            float4 a1 = *reinterpret_cast<const float4*>(&sA[kk][m0 + 4]);
            float4 bv = *reinterpret_cast<const float4*>(&sB[kk][nc]);
            unsigned long long ap[4] = { pk2(a0.x, a0.y), pk2(a0.z, a0.w),
                                         pk2(a1.x, a1.y), pk2(a1.z, a1.w) };
            unsigned long long bp[4] = { pk2(bv.x, bv.x), pk2(bv.y, bv.y),
                                         pk2(bv.z, bv.z), pk2(bv.w, bv.w) };
            #pragma unroll
            for (int i = 0; i < 4; ++i)
                #pragma unroll
                for (int j = 0; j < 4; ++j)
                    fma2(acc[i][j], ap[i], bp[j]);
        }
    }

    const float4 bb = *reinterpret_cast<const float4*>(&bout[n0 + nc]);
    #pragma unroll
    for (int i2 = 0; i2 < 4; ++i2) {
        float lo[4], hi[4];
        #pragma unroll
        for (int j = 0; j < 4; ++j) upk2(acc[i2][j], lo[j], hi[j]);
        const int r0 = bm0 + m0 + 2 * i2;
        float4 w0 = make_float4(lo[0] + bb.x, lo[1] + bb.y, lo[2] + bb.z, lo[3] + bb.w);
        float4 w1 = make_float4(hi[0] + bb.x, hi[1] + bb.y, hi[2] + bb.z, hi[3] + bb.w);
        *reinterpret_cast<float4*>(out + (size_t)r0 * VDIM + n0 + nc) = w0;
        *reinterpret_cast<float4*>(out + (size_t)(r0 + 1) * VDIM + n0 + nc) = w1;
    }
}

// ---------------- tail copy: hT and cT ----------------------------------------
__global__ void copy_tail_kernel(float* __restrict__ out) {
    const size_t base = (size_t)LSEQ * BATCH * VDIM;
    const size_t n = (size_t)BATCH * HDIM;
    const float* hlast = g_Hall + (size_t)(LSEQ - 1) * BATCH * HDIM;
    for (size_t i = (size_t)blockIdx.x * blockDim.x + threadIdx.x; i < n;
         i += (size_t)gridDim.x * blockDim.x) {
        out[base + i] = hlast[i];
        out[base + n + i] = g_C[i];
    }
}

// ---------------- launch -------------------------------------------------------
extern "C" void kernel_launch(void* const* d_in, const int* in_sizes, int n_in,
                              void* d_out, int out_size) {
    const int*   input = (const int*)  d_in[0];
    const float* h0    = (const float*)d_in[1];
    const float* c0    = (const float*)d_in[2];
    const float* emb   = (const float*)d_in[3];
    const float* W_ih  = (const float*)d_in[4];
    const float* W_hh  = (const float*)d_in[5];
    const float* b_ih  = (const float*)d_in[6];
    const float* b_hh  = (const float*)d_in[7];
    const float* W_out = (const float*)d_in[8];
    const float* b_out = (const float*)d_in[9];
    float* out = (float*)d_out;

    repack_kernel<<<2048, 256>>>(W_ih, W_hh, b_ih, b_hh);

    dim3 stepGrid(BATCH / 64, NG / 64);  // 128 x 32
    for (int t = 0; t < LSEQ; ++t) {
        lstm_step_kernel<<<stepGrid, 128>>>(t, h0, c0, input, emb);
    }

    dim3 outGrid((LSEQ * BATCH) / 64, VDIM / 64);  // 6144 x 2
    out_gemm_kernel<<<outGrid, 128>>>(W_out, b_out, out);

    copy_tail_kernel<<<4096, 256>>>(out);
}